// round 1
// baseline (speedup 1.0000x reference)
#include <cuda_runtime.h>
#include <math.h>
#include <stddef.h>

// Problem dims (fixed by the reference)
#define T_DIM 4096
#define H_DIM 2048
#define K_DIM 1024
#define V_DIM 1024
#define O_DIM 2048

// Static scratch (no cudaMalloc allowed):
// layout: q[T*K] | k[T*K] | g[T*K] | v[T*V] | opre[T*V] | state_dump[K*V]
__device__ float g_scratch[(size_t)3 * T_DIM * K_DIM +
                           (size_t)2 * T_DIM * V_DIM +
                           (size_t)K_DIM * V_DIM];

// ---------------------------------------------------------------------------
// Generic NT SGEMM: C[M,N] = A[M,Kd] * B[N,Kd]^T + bias[N], optional sigmoid.
// Both operands K-major (row-major with Kd contiguous) -> fully coalesced.
// 128x128 tile, BK=16, 256 threads, 8x8 microtile per thread.
// All dims used here are multiples of 128/16 -> no bounds checks.
// ---------------------------------------------------------------------------
__global__ void __launch_bounds__(256) gemm_nt_kernel(
    const float* __restrict__ A, const float* __restrict__ B,
    const float* __restrict__ bias, float* __restrict__ C,
    int M, int N, int Kd, int act)
{
    __shared__ float As[16][132];   // +4 pad: 2-way store conflicts, 16B-aligned rows
    __shared__ float Bs[16][132];

    const int tid = threadIdx.x;
    const int bm = blockIdx.y * 128;
    const int bn = blockIdx.x * 128;
    const int ty = tid >> 4;        // 0..15
    const int tx = tid & 15;        // 0..15

    float acc[8][8];
#pragma unroll
    for (int i = 0; i < 8; i++)
#pragma unroll
        for (int j = 0; j < 8; j++) acc[i][j] = 0.f;

    const int r0 = tid >> 2;            // 0..63
    const int cs = (tid & 3) * 4;       // 0,4,8,12

    for (int k0 = 0; k0 < Kd; k0 += 16) {
#pragma unroll
        for (int i = 0; i < 2; i++) {
            const int r = r0 + i * 64;
            float4 a = *(const float4*)(A + (size_t)(bm + r) * Kd + k0 + cs);
            As[cs + 0][r] = a.x; As[cs + 1][r] = a.y;
            As[cs + 2][r] = a.z; As[cs + 3][r] = a.w;
            float4 b = *(const float4*)(B + (size_t)(bn + r) * Kd + k0 + cs);
            Bs[cs + 0][r] = b.x; Bs[cs + 1][r] = b.y;
            Bs[cs + 2][r] = b.z; Bs[cs + 3][r] = b.w;
        }
        __syncthreads();

#pragma unroll
        for (int kk = 0; kk < 16; kk++) {
            float4 a0 = *(const float4*)&As[kk][ty * 8];
            float4 a1 = *(const float4*)&As[kk][ty * 8 + 4];
            float4 b0 = *(const float4*)&Bs[kk][tx * 8];
            float4 b1 = *(const float4*)&Bs[kk][tx * 8 + 4];
            float af[8] = {a0.x, a0.y, a0.z, a0.w, a1.x, a1.y, a1.z, a1.w};
            float bf[8] = {b0.x, b0.y, b0.z, b0.w, b1.x, b1.y, b1.z, b1.w};
#pragma unroll
            for (int i = 0; i < 8; i++)
#pragma unroll
                for (int j = 0; j < 8; j++)
                    acc[i][j] += af[i] * bf[j];
        }
        __syncthreads();
    }

    // epilogue: bias + optional sigmoid, vectorized stores
#pragma unroll
    for (int i = 0; i < 8; i++) {
        const int row = bm + ty * 8 + i;
        float out[8];
#pragma unroll
        for (int j = 0; j < 8; j++) {
            float c = acc[i][j] + bias[bn + tx * 8 + j];
            if (act) c = 1.f / (1.f + expf(-c));
            out[j] = c;
        }
        float4* dst = (float4*)(C + (size_t)row * N + bn + tx * 8);
        dst[0] = make_float4(out[0], out[1], out[2], out[3]);
        dst[1] = make_float4(out[4], out[5], out[6], out[7]);
    }
}

// ---------------------------------------------------------------------------
// Gated linear-recurrence scan.
//   state[k][v] = state[k][v] * g_t[k] + k_t[k] * v_t[v]
//   out_t[v]    = sum_k q_t[k] * state[k][v]
// Grid: 128 CTAs x 256 threads. CTA b owns V columns [8b, 8b+8).
// Thread tid owns K rows [4*tid, 4*tid+4) -> 4x8 fp32 state in registers.
// Each thread's q/k/g needs are exactly its own coalesced float4 -> no SMEM
// staging. Inputs software-pipelined one step ahead. One barrier/step for the
// cross-warp out reduction (parity double-buffered SMEM).
// ---------------------------------------------------------------------------
__global__ void __launch_bounds__(256, 1) scan_kernel(
    const float* __restrict__ q, const float* __restrict__ kv_k,
    const float* __restrict__ gv, const float* __restrict__ vv,
    float* __restrict__ opre, float* __restrict__ state_out)
{
    __shared__ float sred[2][8][8];   // [parity][warp][vcol]

    const int tid  = threadIdx.x;
    const int wid  = tid >> 5;
    const int lane = tid & 31;
    const int vbase = blockIdx.x * 8;
    const int krow  = tid * 4;

    float s[4][8];
#pragma unroll
    for (int i = 0; i < 4; i++)
#pragma unroll
        for (int j = 0; j < 8; j++) s[i][j] = 0.f;

    // prefetch step 0
    float4 pq = *(const float4*)(q    + krow);
    float4 pk = *(const float4*)(kv_k + krow);
    float4 pg = *(const float4*)(gv   + krow);
    float4 pv0 = *(const float4*)(vv + vbase);
    float4 pv1 = *(const float4*)(vv + vbase + 4);

    for (int t = 0; t < T_DIM; t++) {
        const float4 cq = pq, ck = pk, cg = pg, cv0 = pv0, cv1 = pv1;

        if (t + 1 < T_DIM) {
            const size_t off = (size_t)(t + 1) * K_DIM + krow;
            pq = *(const float4*)(q    + off);
            pk = *(const float4*)(kv_k + off);
            pg = *(const float4*)(gv   + off);
            const size_t voff = (size_t)(t + 1) * V_DIM + vbase;
            pv0 = *(const float4*)(vv + voff);
            pv1 = *(const float4*)(vv + voff + 4);
        }

        const float qa[4] = {cq.x, cq.y, cq.z, cq.w};
        const float ka[4] = {ck.x, ck.y, ck.z, ck.w};
        const float ga[4] = {cg.x, cg.y, cg.z, cg.w};
        const float vr[8] = {cv0.x, cv0.y, cv0.z, cv0.w,
                             cv1.x, cv1.y, cv1.z, cv1.w};

        float po[8] = {0.f, 0.f, 0.f, 0.f, 0.f, 0.f, 0.f, 0.f};
#pragma unroll
        for (int i = 0; i < 4; i++) {
#pragma unroll
            for (int j = 0; j < 8; j++) {
                s[i][j] = fmaf(s[i][j], ga[i], ka[i] * vr[j]);
                po[j]   = fmaf(qa[i], s[i][j], po[j]);
            }
        }

        // warp butterfly reduce 8 values over 32 lanes
#pragma unroll
        for (int j = 0; j < 8; j++) {
            float x = po[j];
            x += __shfl_xor_sync(0xffffffffu, x, 16);
            x += __shfl_xor_sync(0xffffffffu, x, 8);
            x += __shfl_xor_sync(0xffffffffu, x, 4);
            x += __shfl_xor_sync(0xffffffffu, x, 2);
            x += __shfl_xor_sync(0xffffffffu, x, 1);
            if (lane == 0) sred[t & 1][wid][j] = x;
        }
        __syncthreads();
        if (tid < 8) {
            float x = 0.f;
#pragma unroll
            for (int w = 0; w < 8; w++) x += sred[t & 1][w][tid];
            opre[(size_t)t * V_DIM + vbase + tid] = x;
        }
        // parity double-buffer makes this the only barrier per step
    }

    // final state -> global (K,V) row-major, matching reference final_state
#pragma unroll
    for (int i = 0; i < 4; i++) {
        float4 lo = make_float4(s[i][0], s[i][1], s[i][2], s[i][3]);
        float4 hi = make_float4(s[i][4], s[i][5], s[i][6], s[i][7]);
        float4* dst = (float4*)(state_out + (size_t)(krow + i) * V_DIM + vbase);
        dst[0] = lo;
        dst[1] = hi;
    }
}

// ---------------------------------------------------------------------------
// Launch: 4 projection GEMMs -> scan -> output GEMM. All on the capture stream.
// ---------------------------------------------------------------------------
extern "C" void kernel_launch(void* const* d_in, const int* in_sizes, int n_in,
                              void* d_out, int out_size)
{
    const float* X  = (const float*)d_in[0];
    const float* Wq = (const float*)d_in[1];
    const float* bq = (const float*)d_in[2];
    const float* Wk = (const float*)d_in[3];
    const float* bk = (const float*)d_in[4];
    const float* Wv = (const float*)d_in[5];
    const float* bv = (const float*)d_in[6];
    const float* Wg = (const float*)d_in[7];
    const float* bg = (const float*)d_in[8];
    const float* Wo = (const float*)d_in[9];
    const float* bo = (const float*)d_in[10];
    float* out = (float*)d_out;

    float* scratch = 0;
    cudaGetSymbolAddress((void**)&scratch, g_scratch);
    float* qb    = scratch;
    float* kb    = qb   + (size_t)T_DIM * K_DIM;
    float* gb    = kb   + (size_t)T_DIM * K_DIM;
    float* vb    = gb   + (size_t)T_DIM * K_DIM;
    float* opre  = vb   + (size_t)T_DIM * V_DIM;
    float* sdump = opre + (size_t)T_DIM * V_DIM;

    const size_t out_main = (size_t)T_DIM * O_DIM;
    const size_t out_full = out_main + (size_t)K_DIM * V_DIM;
    float* state_out = ((size_t)out_size >= out_full) ? (out + out_main) : sdump;

    dim3 blk(256);
    // projections: q (linear), k (sigmoid), g (sigmoid), v (linear)
    gemm_nt_kernel<<<dim3(K_DIM / 128, T_DIM / 128), blk>>>(X, Wq, bq, qb, T_DIM, K_DIM, H_DIM, 0);
    gemm_nt_kernel<<<dim3(K_DIM / 128, T_DIM / 128), blk>>>(X, Wk, bk, kb, T_DIM, K_DIM, H_DIM, 1);
    gemm_nt_kernel<<<dim3(K_DIM / 128, T_DIM / 128), blk>>>(X, Wg, bg, gb, T_DIM, K_DIM, H_DIM, 1);
    gemm_nt_kernel<<<dim3(V_DIM / 128, T_DIM / 128), blk>>>(X, Wv, bv, vb, T_DIM, V_DIM, H_DIM, 0);

    // sequential gated scan (register-resident state, one wave of 128 CTAs)
    scan_kernel<<<128, blk>>>(qb, kb, gb, vb, opre, state_out);

    // output projection
    gemm_nt_kernel<<<dim3(O_DIM / 128, T_DIM / 128), blk>>>(opre, Wo, bo, out, T_DIM, O_DIM, V_DIM, 0);
}

// round 2
// speedup vs baseline: 1.9231x; 1.9231x over previous
#include <cuda_runtime.h>
#include <cuda_fp16.h>
#include <math.h>
#include <stddef.h>
#include <stdint.h>

// Problem dims (fixed by the reference)
#define T_DIM 4096
#define H_DIM 2048
#define K_DIM 1024
#define V_DIM 1024
#define O_DIM 2048

// Static scratch: q[T*K] | k[T*K] | g[T*K] | v[T*V] | opre[T*V] | state_dump[K*V]
__device__ float g_scratch[(size_t)3 * T_DIM * K_DIM +
                           (size_t)2 * T_DIM * V_DIM +
                           (size_t)K_DIM * V_DIM];

// ---------------------------------------------------------------------------
// Packed fp32x2 helpers (Blackwell sm_100+; ptxas never auto-fuses these)
// ---------------------------------------------------------------------------
__device__ __forceinline__ unsigned long long pk2(float lo, float hi) {
    unsigned long long r;
    asm("mov.b64 %0, {%1, %2};" : "=l"(r) : "f"(lo), "f"(hi));
    return r;
}
__device__ __forceinline__ void upk2(unsigned long long v, float& lo, float& hi) {
    asm("mov.b64 {%0, %1}, %2;" : "=f"(lo), "=f"(hi) : "l"(v));
}
__device__ __forceinline__ unsigned long long fma2(unsigned long long a,
                                                   unsigned long long b,
                                                   unsigned long long c) {
    unsigned long long d;
    asm("fma.rn.f32x2 %0, %1, %2, %3;" : "=l"(d) : "l"(a), "l"(b), "l"(c));
    return d;
}
__device__ __forceinline__ unsigned long long mul2(unsigned long long a,
                                                   unsigned long long b) {
    unsigned long long d;
    asm("mul.rn.f32x2 %0, %1, %2;" : "=l"(d) : "l"(a), "l"(b));
    return d;
}

// ---------------------------------------------------------------------------
// Tensor-core helpers
// ---------------------------------------------------------------------------
__device__ __forceinline__ void ldm_x4(uint32_t* r, const __half* p) {
    uint32_t addr = (uint32_t)__cvta_generic_to_shared(p);
    asm volatile("ldmatrix.sync.aligned.m8n8.x4.shared.b16 {%0,%1,%2,%3}, [%4];"
                 : "=r"(r[0]), "=r"(r[1]), "=r"(r[2]), "=r"(r[3])
                 : "r"(addr));
}
__device__ __forceinline__ void mma16816(float* d, const uint32_t* a, const uint32_t* b) {
    asm volatile(
        "mma.sync.aligned.m16n8k16.row.col.f32.f16.f16.f32 "
        "{%0,%1,%2,%3}, {%4,%5,%6,%7}, {%8,%9}, {%0,%1,%2,%3};"
        : "+f"(d[0]), "+f"(d[1]), "+f"(d[2]), "+f"(d[3])
        : "r"(a[0]), "r"(a[1]), "r"(a[2]), "r"(a[3]), "r"(b[0]), "r"(b[1]));
}

// ---------------------------------------------------------------------------
// fp16 tensor-core NT GEMM: C[M,N] = A[M,Kd] * B[N,Kd]^T + bias[N] (opt sigmoid)
// fp32 in/out; operands rounded to fp16 (10-bit mantissa = tf32) at smem fill;
// fp32 accumulation in the MMA. 128x128 tile, BK=32, 256 thr (8 warps, 2x4),
// warp tile 64x32 via m16n8k16. Row pitch 40 halves -> conflict-free ldmatrix.
// ---------------------------------------------------------------------------
#define KP 40
__global__ void __launch_bounds__(256) gemm_f16_nt(
    const float* __restrict__ A, const float* __restrict__ B,
    const float* __restrict__ bias, float* __restrict__ C,
    int M, int N, int Kd, int act)
{
    __shared__ __half As[128 * KP];
    __shared__ __half Bs[128 * KP];

    const int tid = threadIdx.x;
    const int lane = tid & 31;
    const int wid = tid >> 5;
    const int warpM = wid >> 2;     // 0..1
    const int warpN = wid & 3;      // 0..3
    const int bm = blockIdx.y * 128;
    const int bn = blockIdx.x * 128;

    float acc[4][4][4];
#pragma unroll
    for (int a = 0; a < 4; a++)
#pragma unroll
        for (int b = 0; b < 4; b++)
#pragma unroll
            for (int c = 0; c < 4; c++) acc[a][b][c] = 0.f;

    const int lr = tid >> 3;         // 0..31 (row within 32-row pass)
    const int lc = (tid & 7) * 4;    // 0,4,..28 (fp32 col)

    float4 av[4], bv[4];
#pragma unroll
    for (int p = 0; p < 4; p++) {
        av[p] = *(const float4*)(A + (size_t)(bm + lr + p * 32) * Kd + lc);
        bv[p] = *(const float4*)(B + (size_t)(bn + lr + p * 32) * Kd + lc);
    }

    const int iters = Kd / 32;
    for (int it = 0; it < iters; ++it) {
        // convert + store current tile
#pragma unroll
        for (int p = 0; p < 4; p++) {
            const int r = lr + p * 32;
            *(__half2*)&As[r * KP + lc]     = __floats2half2_rn(av[p].x, av[p].y);
            *(__half2*)&As[r * KP + lc + 2] = __floats2half2_rn(av[p].z, av[p].w);
            *(__half2*)&Bs[r * KP + lc]     = __floats2half2_rn(bv[p].x, bv[p].y);
            *(__half2*)&Bs[r * KP + lc + 2] = __floats2half2_rn(bv[p].z, bv[p].w);
        }
        __syncthreads();

        if (it + 1 < iters) {
            const int k0 = (it + 1) * 32;
#pragma unroll
            for (int p = 0; p < 4; p++) {
                av[p] = *(const float4*)(A + (size_t)(bm + lr + p * 32) * Kd + k0 + lc);
                bv[p] = *(const float4*)(B + (size_t)(bn + lr + p * 32) * Kd + k0 + lc);
            }
        }

#pragma unroll
        for (int ks = 0; ks < 2; ks++) {
            const int k0 = ks * 16;
            uint32_t afr[4][4];
            uint32_t bfr[4][2];
#pragma unroll
            for (int fm = 0; fm < 4; fm++) {
                const __half* p = &As[(warpM * 64 + fm * 16 + (lane & 7) +
                                       ((lane >> 3) & 1) * 8) * KP +
                                      k0 + (lane >> 4) * 8];
                ldm_x4(afr[fm], p);
            }
#pragma unroll
            for (int fp = 0; fp < 2; fp++) {
                uint32_t r[4];
                const __half* p = &Bs[(warpN * 32 + fp * 16 + (lane & 7) +
                                       (lane >> 4) * 8) * KP +
                                      k0 + ((lane >> 3) & 1) * 8];
                ldm_x4(r, p);
                bfr[2 * fp][0] = r[0];     bfr[2 * fp][1] = r[1];
                bfr[2 * fp + 1][0] = r[2]; bfr[2 * fp + 1][1] = r[3];
            }
#pragma unroll
            for (int fm = 0; fm < 4; fm++)
#pragma unroll
                for (int fn = 0; fn < 4; fn++)
                    mma16816(acc[fm][fn], afr[fm], bfr[fn]);
        }
        __syncthreads();
    }

    // epilogue: bias + optional sigmoid, float2 stores
#pragma unroll
    for (int fm = 0; fm < 4; fm++)
#pragma unroll
        for (int fn = 0; fn < 4; fn++)
#pragma unroll
            for (int h = 0; h < 2; h++) {
                const int row = bm + warpM * 64 + fm * 16 + (lane >> 2) + h * 8;
                const int col = bn + warpN * 32 + fn * 8 + (lane & 3) * 2;
                float c0 = acc[fm][fn][2 * h]     + __ldg(&bias[col]);
                float c1 = acc[fm][fn][2 * h + 1] + __ldg(&bias[col + 1]);
                if (act) {
                    c0 = 1.f / (1.f + expf(-c0));
                    c1 = 1.f / (1.f + expf(-c1));
                }
                *(float2*)(C + (size_t)row * N + col) = make_float2(c0, c1);
            }
}

// ---------------------------------------------------------------------------
// Gated linear-recurrence scan with packed fp32x2 math.
//   state[k][v] = state[k][v]*g_t[k] + k_t[k]*v_t[v];  out_t = q_t . state
// 128 CTAs x 256 thr. CTA owns 8 V-cols; thread owns 4 K-rows -> 4x8 fp32
// state in packed f32x2 registers. Per step: 48 packed FMA-pipe issues/thread
// (was 96 scalar). Reduction: value-halving butterfly (xor4/2/1 -> one value
// per lane at index lane&7, then xor8/16) = 9 SHFL (was 40). One barrier per
// TWO steps via 4 parity smem buffers.
// ---------------------------------------------------------------------------
__global__ void __launch_bounds__(256, 1) scan_kernel(
    const float* __restrict__ q, const float* __restrict__ kv_k,
    const float* __restrict__ gv, const float* __restrict__ vv,
    float* __restrict__ opre, float* __restrict__ state_out)
{
    __shared__ float sred[4][8][8];   // [parity4][warp][vcol]

    const int tid  = threadIdx.x;
    const int wid  = tid >> 5;
    const int lane = tid & 31;
    const int vbase = blockIdx.x * 8;
    const int krow  = tid * 4;

    unsigned long long s2[4][4];
#pragma unroll
    for (int i = 0; i < 4; i++)
#pragma unroll
        for (int j = 0; j < 4; j++) s2[i][j] = pk2(0.f, 0.f);

    // prefetch step 0
    float4 pq = *(const float4*)(q    + krow);
    float4 pk = *(const float4*)(kv_k + krow);
    float4 pg = *(const float4*)(gv   + krow);
    float4 pv0 = *(const float4*)(vv + vbase);
    float4 pv1 = *(const float4*)(vv + vbase + 4);

    for (int t = 0; t < T_DIM; t += 2) {
#pragma unroll
        for (int sub = 0; sub < 2; sub++) {
            const int tt = t + sub;
            const float4 cq = pq, ck = pk, cg = pg, cv0 = pv0, cv1 = pv1;

            if (tt + 1 < T_DIM) {
                const size_t off = (size_t)(tt + 1) * K_DIM + krow;
                pq = *(const float4*)(q    + off);
                pk = *(const float4*)(kv_k + off);
                pg = *(const float4*)(gv   + off);
                const size_t voff = (size_t)(tt + 1) * V_DIM + vbase;
                pv0 = *(const float4*)(vv + voff);
                pv1 = *(const float4*)(vv + voff + 4);
            }

            const float qa[4] = {cq.x, cq.y, cq.z, cq.w};
            const float ka[4] = {ck.x, ck.y, ck.z, ck.w};
            const float ga[4] = {cg.x, cg.y, cg.z, cg.w};
            unsigned long long v2[4];
            v2[0] = pk2(cv0.x, cv0.y);
            v2[1] = pk2(cv0.z, cv0.w);
            v2[2] = pk2(cv1.x, cv1.y);
            v2[3] = pk2(cv1.z, cv1.w);

            unsigned long long po2[4];
#pragma unroll
            for (int j = 0; j < 4; j++) po2[j] = pk2(0.f, 0.f);

#pragma unroll
            for (int i = 0; i < 4; i++) {
                const unsigned long long kk = pk2(ka[i], ka[i]);
                const unsigned long long gg = pk2(ga[i], ga[i]);
                const unsigned long long qq = pk2(qa[i], qa[i]);
#pragma unroll
                for (int j = 0; j < 4; j++) {
                    s2[i][j] = fma2(s2[i][j], gg, mul2(kk, v2[j]));
                    po2[j]   = fma2(qq, s2[i][j], po2[j]);
                }
            }

            // unpack to 8 scalars
            float po[8];
#pragma unroll
            for (int j = 0; j < 4; j++) upk2(po2[j], po[2 * j], po[2 * j + 1]);

            // value-halving butterfly: after xor4/2/1 lane holds sum of value
            // (lane&7) over its 8-lane group; xor8/16 finish the 32-lane sum.
            float t4[4];
#pragma unroll
            for (int j = 0; j < 4; j++) {
                float send = (lane & 4) ? po[j] : po[j + 4];
                float recv = __shfl_xor_sync(0xffffffffu, send, 4);
                t4[j] = ((lane & 4) ? po[j + 4] : po[j]) + recv;
            }
            float t2[2];
#pragma unroll
            for (int j = 0; j < 2; j++) {
                float send = (lane & 2) ? t4[j] : t4[j + 2];
                float recv = __shfl_xor_sync(0xffffffffu, send, 2);
                t2[j] = ((lane & 2) ? t4[j + 2] : t4[j]) + recv;
            }
            float r1;
            {
                float send = (lane & 1) ? t2[0] : t2[1];
                float recv = __shfl_xor_sync(0xffffffffu, send, 1);
                r1 = ((lane & 1) ? t2[1] : t2[0]) + recv;
            }
            r1 += __shfl_xor_sync(0xffffffffu, r1, 8);
            r1 += __shfl_xor_sync(0xffffffffu, r1, 16);

            if (lane < 8) sred[tt & 3][wid][lane] = r1;
        }

        __syncthreads();
        if (tid < 16) {
            const int tt = t + (tid >> 3);
            const int j = tid & 7;
            float x = 0.f;
#pragma unroll
            for (int w = 0; w < 8; w++) x += sred[tt & 3][w][j];
            opre[(size_t)tt * V_DIM + vbase + j] = x;
        }
        // buffers (t&3),(t+1&3) reused only after the NEXT barrier -> safe
    }

    // final state -> global (K,V) row-major
#pragma unroll
    for (int i = 0; i < 4; i++) {
        float s[8];
#pragma unroll
        for (int j = 0; j < 4; j++) upk2(s2[i][j], s[2 * j], s[2 * j + 1]);
        float4* dst = (float4*)(state_out + (size_t)(krow + i) * V_DIM + vbase);
        dst[0] = make_float4(s[0], s[1], s[2], s[3]);
        dst[1] = make_float4(s[4], s[5], s[6], s[7]);
    }
}

// ---------------------------------------------------------------------------
extern "C" void kernel_launch(void* const* d_in, const int* in_sizes, int n_in,
                              void* d_out, int out_size)
{
    const float* X  = (const float*)d_in[0];
    const float* Wq = (const float*)d_in[1];
    const float* bq = (const float*)d_in[2];
    const float* Wk = (const float*)d_in[3];
    const float* bk = (const float*)d_in[4];
    const float* Wv = (const float*)d_in[5];
    const float* bv = (const float*)d_in[6];
    const float* Wg = (const float*)d_in[7];
    const float* bg = (const float*)d_in[8];
    const float* Wo = (const float*)d_in[9];
    const float* bo = (const float*)d_in[10];
    float* out = (float*)d_out;

    float* scratch = 0;
    cudaGetSymbolAddress((void**)&scratch, g_scratch);
    float* qb    = scratch;
    float* kb    = qb   + (size_t)T_DIM * K_DIM;
    float* gb    = kb   + (size_t)T_DIM * K_DIM;
    float* vb    = gb   + (size_t)T_DIM * K_DIM;
    float* opre  = vb   + (size_t)T_DIM * V_DIM;
    float* sdump = opre + (size_t)T_DIM * V_DIM;

    const size_t out_main = (size_t)T_DIM * O_DIM;
    const size_t out_full = out_main + (size_t)K_DIM * V_DIM;
    float* state_out = ((size_t)out_size >= out_full) ? (out + out_main) : sdump;

    dim3 blk(256);
    gemm_f16_nt<<<dim3(K_DIM / 128, T_DIM / 128), blk>>>(X, Wq, bq, qb, T_DIM, K_DIM, H_DIM, 0);
    gemm_f16_nt<<<dim3(K_DIM / 128, T_DIM / 128), blk>>>(X, Wk, bk, kb, T_DIM, K_DIM, H_DIM, 1);
    gemm_f16_nt<<<dim3(K_DIM / 128, T_DIM / 128), blk>>>(X, Wg, bg, gb, T_DIM, K_DIM, H_DIM, 1);
    gemm_f16_nt<<<dim3(V_DIM / 128, T_DIM / 128), blk>>>(X, Wv, bv, vb, T_DIM, V_DIM, H_DIM, 0);

    scan_kernel<<<128, blk>>>(qb, kb, gb, vb, opre, state_out);

    gemm_f16_nt<<<dim3(O_DIM / 128, T_DIM / 128), blk>>>(opre, Wo, bo, out, T_DIM, O_DIM, V_DIM, 0);
}

// round 4
// speedup vs baseline: 2.1402x; 1.1129x over previous
#include <cuda_runtime.h>
#include <cuda_fp16.h>
#include <math.h>
#include <stddef.h>
#include <stdint.h>

// Problem dims (fixed by the reference)
#define T_DIM 4096
#define H_DIM 2048
#define K_DIM 1024
#define V_DIM 1024
#define O_DIM 2048

// fp32 scratch: q[T*K] | k[T*K] | g[T*K] | v[T*V] | opre[T*V] | state_dump[K*V]
__device__ __align__(16) float g_scratch[(size_t)3 * T_DIM * K_DIM +
                                         (size_t)2 * T_DIM * V_DIM +
                                         (size_t)K_DIM * V_DIM];
// fp16 scratch: Xh[T*H] | Wqh | Wkh | Wgh | Wvh (K*H each) | Woh[O*V] | opreh[T*V]
__device__ __align__(16) __half g_scratch_h[(size_t)T_DIM * H_DIM +
                                            (size_t)4 * K_DIM * H_DIM +
                                            (size_t)O_DIM * V_DIM +
                                            (size_t)T_DIM * V_DIM];

// ---------------------------------------------------------------------------
// Packed fp32x2 helpers (sm_100+)
// ---------------------------------------------------------------------------
__device__ __forceinline__ unsigned long long pk2(float lo, float hi) {
    unsigned long long r;
    asm("mov.b64 %0, {%1, %2};" : "=l"(r) : "f"(lo), "f"(hi));
    return r;
}
__device__ __forceinline__ void upk2(unsigned long long v, float& lo, float& hi) {
    asm("mov.b64 {%0, %1}, %2;" : "=f"(lo), "=f"(hi) : "l"(v));
}
__device__ __forceinline__ unsigned long long fma2(unsigned long long a,
                                                   unsigned long long b,
                                                   unsigned long long c) {
    unsigned long long d;
    asm("fma.rn.f32x2 %0, %1, %2, %3;" : "=l"(d) : "l"(a), "l"(b), "l"(c));
    return d;
}
__device__ __forceinline__ unsigned long long mul2(unsigned long long a,
                                                   unsigned long long b) {
    unsigned long long d;
    asm("mul.rn.f32x2 %0, %1, %2;" : "=l"(d) : "l"(a), "l"(b));
    return d;
}

// ---------------------------------------------------------------------------
// Tensor-core + cp.async helpers
// ---------------------------------------------------------------------------
__device__ __forceinline__ void ldm_x4(uint32_t* r, const __half* p) {
    uint32_t addr = (uint32_t)__cvta_generic_to_shared(p);
    asm volatile("ldmatrix.sync.aligned.m8n8.x4.shared.b16 {%0,%1,%2,%3}, [%4];"
                 : "=r"(r[0]), "=r"(r[1]), "=r"(r[2]), "=r"(r[3])
                 : "r"(addr));
}
__device__ __forceinline__ void mma16816(float* d, const uint32_t* a, const uint32_t* b) {
    asm volatile(
        "mma.sync.aligned.m16n8k16.row.col.f32.f16.f16.f32 "
        "{%0,%1,%2,%3}, {%4,%5,%6,%7}, {%8,%9}, {%0,%1,%2,%3};"
        : "+f"(d[0]), "+f"(d[1]), "+f"(d[2]), "+f"(d[3])
        : "r"(a[0]), "r"(a[1]), "r"(a[2]), "r"(a[3]), "r"(b[0]), "r"(b[1]));
}
__device__ __forceinline__ void cp_async16(__half* smem_dst, const __half* gsrc) {
    uint32_t d = (uint32_t)__cvta_generic_to_shared(smem_dst);
    asm volatile("cp.async.cg.shared.global [%0], [%1], 16;" :: "r"(d), "l"(gsrc));
}
#define CP_COMMIT() asm volatile("cp.async.commit_group;")
#define CP_WAIT(n)  asm volatile("cp.async.wait_group %0;" :: "n"(n))

// ---------------------------------------------------------------------------
// fp32 -> fp16 convert, vectorized (float4 in, 4x half = 8B out)
// ---------------------------------------------------------------------------
__global__ void f2h_kernel(const float* __restrict__ src, __half* __restrict__ dst,
                           int n4)
{
    int i = blockIdx.x * blockDim.x + threadIdx.x;
    const int stride = gridDim.x * blockDim.x;
    for (; i < n4; i += stride) {
        float4 v = ((const float4*)src)[i];
        __half2 h0 = __floats2half2_rn(v.x, v.y);
        __half2 h1 = __floats2half2_rn(v.z, v.w);
        uint2 u;
        u.x = *reinterpret_cast<unsigned*>(&h0);
        u.y = *reinterpret_cast<unsigned*>(&h1);
        ((uint2*)dst)[i] = u;
    }
}

// ---------------------------------------------------------------------------
// fp16-input NT GEMM: C[M,N] = A[M,Kd] * B[N,Kd]^T + bias[N], optional sigmoid.
// A,B pre-converted to fp16 (K-major). cp.async 2-stage double buffer, BK=32,
// 128x128 tile, 256 thr (8 warps 2x4), warp tile 64x32 via m16n8k16, fp32 acc.
// Row pitch KP=40 halves (80B = 5x16B) -> aligned cp.async + conflict-free
// ldmatrix. 2 CTAs/SM -> grid runs in ~one wave.
// ---------------------------------------------------------------------------
#define KP 40
__global__ void __launch_bounds__(256, 2) gemm_h_nt(
    const __half* __restrict__ A, const __half* __restrict__ B,
    const float* __restrict__ bias, float* __restrict__ C,
    int M, int N, int Kd, int act)
{
    __shared__ __half As[2][128 * KP];
    __shared__ __half Bs[2][128 * KP];

    const int tid = threadIdx.x;
    const int lane = tid & 31;
    const int wid = tid >> 5;
    const int warpM = wid >> 2;     // 0..1
    const int warpN = wid & 3;      // 0..3
    const int bm = blockIdx.y * 128;
    const int bn = blockIdx.x * 128;

    float acc[4][4][4];
#pragma unroll
    for (int a = 0; a < 4; a++)
#pragma unroll
        for (int b = 0; b < 4; b++)
#pragma unroll
            for (int c = 0; c < 4; c++) acc[a][b][c] = 0.f;

    const int iters = Kd / 32;

    // stage loader: 128 rows x 32 halves (4x 16B chunks/row), A and B
#define LOAD_TILE(buf, k0)                                                     \
    {                                                                          \
        _Pragma("unroll")                                                      \
        for (int p = 0; p < 2; p++) {                                          \
            const int c = tid + p * 256;                                       \
            const int row = c >> 2;                                            \
            const int col = (c & 3) * 8;                                       \
            cp_async16(&As[buf][row * KP + col],                               \
                       A + (size_t)(bm + row) * Kd + (k0) + col);              \
            cp_async16(&Bs[buf][row * KP + col],                               \
                       B + (size_t)(bn + row) * Kd + (k0) + col);              \
        }                                                                      \
    }

    LOAD_TILE(0, 0);
    CP_COMMIT();

    for (int it = 0; it < iters; ++it) {
        if (it + 1 < iters) {
            LOAD_TILE((it + 1) & 1, (it + 1) * 32);
            CP_COMMIT();
            CP_WAIT(1);
        } else {
            CP_WAIT(0);
        }
        __syncthreads();

        const __half* Ab = As[it & 1];
        const __half* Bb = Bs[it & 1];
#pragma unroll
        for (int ks = 0; ks < 2; ks++) {
            const int k0 = ks * 16;
            uint32_t afr[4][4];
            uint32_t bfr[4][2];
#pragma unroll
            for (int fm = 0; fm < 4; fm++) {
                const __half* p = &Ab[(warpM * 64 + fm * 16 + (lane & 7) +
                                       ((lane >> 3) & 1) * 8) * KP +
                                      k0 + (lane >> 4) * 8];
                ldm_x4(afr[fm], p);
            }
#pragma unroll
            for (int fp = 0; fp < 2; fp++) {
                uint32_t r[4];
                const __half* p = &Bb[(warpN * 32 + fp * 16 + (lane & 7) +
                                       (lane >> 4) * 8) * KP +
                                      k0 + ((lane >> 3) & 1) * 8];
                ldm_x4(r, p);
                bfr[2 * fp][0] = r[0];     bfr[2 * fp][1] = r[1];
                bfr[2 * fp + 1][0] = r[2]; bfr[2 * fp + 1][1] = r[3];
            }
#pragma unroll
            for (int fm = 0; fm < 4; fm++)
#pragma unroll
                for (int fn = 0; fn < 4; fn++)
                    mma16816(acc[fm][fn], afr[fm], bfr[fn]);
        }
        __syncthreads();
    }
#undef LOAD_TILE

    // epilogue: bias + optional sigmoid
#pragma unroll
    for (int fm = 0; fm < 4; fm++)
#pragma unroll
        for (int fn = 0; fn < 4; fn++)
#pragma unroll
            for (int h = 0; h < 2; h++) {
                const int row = bm + warpM * 64 + fm * 16 + (lane >> 2) + h * 8;
                const int col = bn + warpN * 32 + fn * 8 + (lane & 3) * 2;
                float c0 = acc[fm][fn][2 * h]     + __ldg(&bias[col]);
                float c1 = acc[fm][fn][2 * h + 1] + __ldg(&bias[col + 1]);
                if (act) {
                    c0 = 1.f / (1.f + expf(-c0));
                    c1 = 1.f / (1.f + expf(-c1));
                }
                *(float2*)(C + (size_t)row * N + col) = make_float2(c0, c1);
            }
}

// ---------------------------------------------------------------------------
// Gated linear-recurrence scan, K-packed fp32x2 state, 2 CTAs/SM.
//   state[k][v] = state[k][v]*g_t[k] + k_t[k]*v_t[v];  out_t = q_t . state
// 256 CTAs x 256 thr. CTA owns 4 V-cols (vbase=4*bid); thread owns K rows
// [4*tid,4*tid+4) as 2 packed K-pairs x 4 cols -> 8 u64 state regs.
// q/k/g packed operands are free reinterprets of the float4 load; only v
// needs lane duplication. Reduction: 4 values -> 5 shuffles. One barrier per
// 2 steps (4-deep parity smem). 4 warps/SMSP hides shfl + L2 latency.
// ---------------------------------------------------------------------------
__global__ void __launch_bounds__(256, 2) scan_kernel(
    const float* __restrict__ q, const float* __restrict__ kv_k,
    const float* __restrict__ gv, const float* __restrict__ vv,
    float* __restrict__ opre, float* __restrict__ state_out)
{
    __shared__ float sred[4][8][4];   // [parity4][warp][vcol]

    const int tid  = threadIdx.x;
    const int wid  = tid >> 5;
    const int lane = tid & 31;
    const int vbase = blockIdx.x * 4;
    const int kbase = tid * 4;

    unsigned long long s2[2][4];
#pragma unroll
    for (int ip = 0; ip < 2; ip++)
#pragma unroll
        for (int j = 0; j < 4; j++) s2[ip][j] = pk2(0.f, 0.f);

    // prefetch step 0 (q/k/g as packed pairs via 16B loads)
    ulonglong2 pq = *(const ulonglong2*)(q    + kbase);
    ulonglong2 pk = *(const ulonglong2*)(kv_k + kbase);
    ulonglong2 pg = *(const ulonglong2*)(gv   + kbase);
    float4     pv = *(const float4*)(vv + vbase);

    for (int t = 0; t < T_DIM; t += 2) {
#pragma unroll
        for (int sub = 0; sub < 2; sub++) {
            const int tt = t + sub;
            const ulonglong2 cq = pq, ck = pk, cg = pg;
            const float4 cv = pv;

            if (tt + 1 < T_DIM) {
                const size_t off = (size_t)(tt + 1) * K_DIM + kbase;
                pq = *(const ulonglong2*)(q    + off);
                pk = *(const ulonglong2*)(kv_k + off);
                pg = *(const ulonglong2*)(gv   + off);
                pv = *(const float4*)(vv + (size_t)(tt + 1) * V_DIM + vbase);
            }

            unsigned long long vd[4];
            vd[0] = pk2(cv.x, cv.x);
            vd[1] = pk2(cv.y, cv.y);
            vd[2] = pk2(cv.z, cv.z);
            vd[3] = pk2(cv.w, cv.w);

            unsigned long long po2[4];
#pragma unroll
            for (int j = 0; j < 4; j++) po2[j] = pk2(0.f, 0.f);

#pragma unroll
            for (int ip = 0; ip < 2; ip++) {
                const unsigned long long q2 = ip ? cq.y : cq.x;
                const unsigned long long k2 = ip ? ck.y : ck.x;
                const unsigned long long g2 = ip ? cg.y : cg.x;
#pragma unroll
                for (int j = 0; j < 4; j++) {
                    s2[ip][j] = fma2(s2[ip][j], g2, mul2(k2, vd[j]));
                    po2[j]    = fma2(q2, s2[ip][j], po2[j]);
                }
            }

            float po[4];
#pragma unroll
            for (int j = 0; j < 4; j++) {
                float lo, hi;
                upk2(po2[j], lo, hi);
                po[j] = lo + hi;
            }

            // value-halving butterfly: xor2, xor1 -> lane holds col (lane&3)
            // partial over its 4-lane group; xor4/8/16 finish the warp sum.
            const bool b1 = (lane & 2) != 0;
            float s0 = b1 ? po[0] : po[2];
            float s1 = b1 ? po[1] : po[3];
            float r0 = __shfl_xor_sync(0xffffffffu, s0, 2);
            float r1 = __shfl_xor_sync(0xffffffffu, s1, 2);
            float u0 = (b1 ? po[2] : po[0]) + r0;
            float u1 = (b1 ? po[3] : po[1]) + r1;

            const bool b0 = (lane & 1) != 0;
            float s = b0 ? u0 : u1;
            float rr = __shfl_xor_sync(0xffffffffu, s, 1);
            float r = (b0 ? u1 : u0) + rr;

            r += __shfl_xor_sync(0xffffffffu, r, 4);
            r += __shfl_xor_sync(0xffffffffu, r, 8);
            r += __shfl_xor_sync(0xffffffffu, r, 16);

            if (lane < 4) sred[tt & 3][wid][lane] = r;
        }

        __syncthreads();
        if (tid < 8) {
            const int tt = t + (tid >> 2);
            const int j = tid & 3;
            float x = 0.f;
#pragma unroll
            for (int w = 0; w < 8; w++) x += sred[tt & 3][w][j];
            opre[(size_t)tt * V_DIM + vbase + j] = x;
        }
        // depth-4 buffers: slots for steps t,t+1 are rewritten only two
        // barriers later -> reader has always finished.
    }

    // final state -> global (K,V) row-major
#pragma unroll
    for (int ip = 0; ip < 2; ip++) {
        float lo[4], hi[4];
#pragma unroll
        for (int j = 0; j < 4; j++) upk2(s2[ip][j], lo[j], hi[j]);
        *(float4*)(state_out + (size_t)(kbase + 2 * ip) * V_DIM + vbase) =
            make_float4(lo[0], lo[1], lo[2], lo[3]);
        *(float4*)(state_out + (size_t)(kbase + 2 * ip + 1) * V_DIM + vbase) =
            make_float4(hi[0], hi[1], hi[2], hi[3]);
    }
}

// ---------------------------------------------------------------------------
extern "C" void kernel_launch(void* const* d_in, const int* in_sizes, int n_in,
                              void* d_out, int out_size)
{
    const float* X  = (const float*)d_in[0];
    const float* Wq = (const float*)d_in[1];
    const float* bq = (const float*)d_in[2];
    const float* Wk = (const float*)d_in[3];
    const float* bk = (const float*)d_in[4];
    const float* Wv = (const float*)d_in[5];
    const float* bv = (const float*)d_in[6];
    const float* Wg = (const float*)d_in[7];
    const float* bg = (const float*)d_in[8];
    const float* Wo = (const float*)d_in[9];
    const float* bo = (const float*)d_in[10];
    float* out = (float*)d_out;

    float* scratch = 0;
    cudaGetSymbolAddress((void**)&scratch, g_scratch);
    float* qb    = scratch;
    float* kb    = qb   + (size_t)T_DIM * K_DIM;
    float* gb    = kb   + (size_t)T_DIM * K_DIM;
    float* vb    = gb   + (size_t)T_DIM * K_DIM;
    float* opre  = vb   + (size_t)T_DIM * V_DIM;
    float* sdump = opre + (size_t)T_DIM * V_DIM;

    __half* hscr = 0;
    cudaGetSymbolAddress((void**)&hscr, g_scratch_h);
    __half* Xh    = hscr;
    __half* Wqh   = Xh   + (size_t)T_DIM * H_DIM;
    __half* Wkh   = Wqh  + (size_t)K_DIM * H_DIM;
    __half* Wgh   = Wkh  + (size_t)K_DIM * H_DIM;
    __half* Wvh   = Wgh  + (size_t)K_DIM * H_DIM;
    __half* Woh   = Wvh  + (size_t)K_DIM * H_DIM;
    __half* opreh = Woh  + (size_t)O_DIM * V_DIM;

    const size_t out_main = (size_t)T_DIM * O_DIM;
    const size_t out_full = out_main + (size_t)K_DIM * V_DIM;
    float* state_out = ((size_t)out_size >= out_full) ? (out + out_main) : sdump;

    dim3 blk(256);

    // one-time fp32->fp16 conversions
    f2h_kernel<<<2048, 256>>>(X,  Xh,  (int)((size_t)T_DIM * H_DIM / 4));
    f2h_kernel<<<1024, 256>>>(Wq, Wqh, (int)((size_t)K_DIM * H_DIM / 4));
    f2h_kernel<<<1024, 256>>>(Wk, Wkh, (int)((size_t)K_DIM * H_DIM / 4));
    f2h_kernel<<<1024, 256>>>(Wg, Wgh, (int)((size_t)K_DIM * H_DIM / 4));
    f2h_kernel<<<1024, 256>>>(Wv, Wvh, (int)((size_t)K_DIM * H_DIM / 4));
    f2h_kernel<<<1024, 256>>>(Wo, Woh, (int)((size_t)O_DIM * V_DIM / 4));

    // projections: q (linear), k (sigmoid), g (sigmoid), v (linear)
    gemm_h_nt<<<dim3(K_DIM / 128, T_DIM / 128), blk>>>(Xh, Wqh, bq, qb, T_DIM, K_DIM, H_DIM, 0);
    gemm_h_nt<<<dim3(K_DIM / 128, T_DIM / 128), blk>>>(Xh, Wkh, bk, kb, T_DIM, K_DIM, H_DIM, 1);
    gemm_h_nt<<<dim3(K_DIM / 128, T_DIM / 128), blk>>>(Xh, Wgh, bg, gb, T_DIM, K_DIM, H_DIM, 1);
    gemm_h_nt<<<dim3(V_DIM / 128, T_DIM / 128), blk>>>(Xh, Wvh, bv, vb, T_DIM, V_DIM, H_DIM, 0);

    // sequential gated scan (2 CTAs/SM)
    scan_kernel<<<256, blk>>>(qb, kb, gb, vb, opre, state_out);

    // opre -> fp16, then output projection
    f2h_kernel<<<1024, 256>>>(opre, opreh, (int)((size_t)T_DIM * V_DIM / 4));
    gemm_h_nt<<<dim3(O_DIM / 128, T_DIM / 128), blk>>>(opreh, Woh, bo, out, T_DIM, O_DIM, V_DIM, 0);
}